// round 1
// baseline (speedup 1.0000x reference)
#include <cuda_runtime.h>
#include <math.h>

#define T_DIM 4096
#define C_DIM 1024
#define HF_DIM 4096
#define NH 16
#define HD 64

// ---------------- scratch (module-static, no runtime allocation) ----------------
__device__ float g_xn [T_DIM * C_DIM];       // rmsnorm(x)
__device__ float g_qkv[T_DIM * 3 * C_DIM];   // qkv projection
__device__ float g_y  [T_DIM * C_DIM];       // attention output
__device__ float g_x2 [T_DIM * C_DIM];       // x + attn
__device__ float g_xn2[T_DIM * C_DIM];       // rmsnorm(x2)
__device__ float g_h1 [T_DIM * HF_DIM];      // xn2 @ w1^T (then silu*h3 in-place)
__device__ float g_h3 [T_DIM * HF_DIM];      // xn2 @ w3^T

// ---------------- rmsnorm: one block per row, 256 threads, C=1024 ----------------
__global__ __launch_bounds__(256) void rmsnorm_kernel(const float* __restrict__ x,
                                                      const float* __restrict__ w,
                                                      float* __restrict__ o) {
    int row = blockIdx.x;
    int t = threadIdx.x;
    const float4* xr = (const float4*)(x + (size_t)row * C_DIM);
    float4 v = xr[t];
    float ss = v.x * v.x + v.y * v.y + v.z * v.z + v.w * v.w;
    __shared__ float red[8];
#pragma unroll
    for (int off = 16; off; off >>= 1) ss += __shfl_xor_sync(~0u, ss, off);
    if ((t & 31) == 0) red[t >> 5] = ss;
    __syncthreads();
    if (t < 32) {
        float s2 = (t < 8) ? red[t] : 0.f;
#pragma unroll
        for (int off = 4; off; off >>= 1) s2 += __shfl_xor_sync(~0u, s2, off);
        if (t == 0) red[0] = s2;
    }
    __syncthreads();
    float rn = rsqrtf(red[0] * (1.0f / C_DIM) + 1e-6f);
    float4 wv = ((const float4*)w)[t];
    float4 ov = make_float4(v.x * rn * wv.x, v.y * rn * wv.y, v.z * rn * wv.z, v.w * rn * wv.w);
    ((float4*)(o + (size_t)row * C_DIM))[t] = ov;
}

// ---------------- GEMM: C[M,N] = A[M,K] @ B[N,K]^T (+ R) ----------------
// 128x128 block tile, BK=8, 256 threads, 8x8 per thread. M,N % 128 == 0, K % 8 == 0.
__global__ __launch_bounds__(256) void gemm_tn(const float* __restrict__ A,
                                               const float* __restrict__ B,
                                               const float* __restrict__ R,
                                               float* __restrict__ C,
                                               int M, int N, int K) {
    __shared__ float As[8][132];
    __shared__ float Bs[8][132];
    int tx = threadIdx.x & 15, ty = threadIdx.x >> 4;
    int m0 = blockIdx.y << 7, n0 = blockIdx.x << 7;
    int t = threadIdx.x;
    int lrow = t >> 1;           // 0..127
    int lcol = (t & 1) << 2;     // 0 or 4
    const float* Ag = A + (size_t)(m0 + lrow) * K + lcol;
    const float* Bg = B + (size_t)(n0 + lrow) * K + lcol;
    float acc[8][8] = {};
    for (int k0 = 0; k0 < K; k0 += 8) {
        float4 av = *(const float4*)(Ag + k0);
        float4 bv = *(const float4*)(Bg + k0);
        As[lcol + 0][lrow] = av.x; As[lcol + 1][lrow] = av.y;
        As[lcol + 2][lrow] = av.z; As[lcol + 3][lrow] = av.w;
        Bs[lcol + 0][lrow] = bv.x; Bs[lcol + 1][lrow] = bv.y;
        Bs[lcol + 2][lrow] = bv.z; Bs[lcol + 3][lrow] = bv.w;
        __syncthreads();
#pragma unroll
        for (int kk = 0; kk < 8; kk++) {
            float a[8], b[8];
            *(float4*)&a[0] = *(const float4*)&As[kk][ty * 8];
            *(float4*)&a[4] = *(const float4*)&As[kk][ty * 8 + 4];
            *(float4*)&b[0] = *(const float4*)&Bs[kk][tx * 8];
            *(float4*)&b[4] = *(const float4*)&Bs[kk][tx * 8 + 4];
#pragma unroll
            for (int i = 0; i < 8; i++)
#pragma unroll
                for (int j = 0; j < 8; j++)
                    acc[i][j] = fmaf(a[i], b[j], acc[i][j]);
        }
        __syncthreads();
    }
#pragma unroll
    for (int i = 0; i < 8; i++) {
        size_t off = (size_t)(m0 + ty * 8 + i) * N + n0 + tx * 8;
        float4 r0 = make_float4(acc[i][0], acc[i][1], acc[i][2], acc[i][3]);
        float4 r1 = make_float4(acc[i][4], acc[i][5], acc[i][6], acc[i][7]);
        if (R) {
            float4 q0 = *(const float4*)(R + off);
            float4 q1 = *(const float4*)(R + off + 4);
            r0.x += q0.x; r0.y += q0.y; r0.z += q0.z; r0.w += q0.w;
            r1.x += q1.x; r1.y += q1.y; r1.z += q1.z; r1.w += q1.w;
        }
        *(float4*)(C + off) = r0;
        *(float4*)(C + off + 4) = r1;
    }
}

// ---------------- causal flash attention, fp32, hd=64, 64x64 tiles ----------------
// grid: (T/64, NH), 256 threads. Dynamic smem: 4 tiles of [64][68].
#define APITCH 68
#define ATTN_SMEM (4 * 64 * APITCH * 4)

__global__ __launch_bounds__(256) void flash_attn_kernel(const float* __restrict__ qkv,
                                                         float* __restrict__ y) {
    extern __shared__ float sm[];
    float (*Qs)[APITCH] = (float (*)[APITCH])sm;                       // [d][row]
    float (*Ks)[APITCH] = (float (*)[APITCH])(sm + 64 * APITCH);      // [d][key]
    float (*Vs)[APITCH] = (float (*)[APITCH])(sm + 2 * 64 * APITCH);  // [key][d]
    float (*Ps)[APITCH] = (float (*)[APITCH])(sm + 3 * 64 * APITCH);  // [key][row]
    int h = blockIdx.y;
    int q0 = blockIdx.x << 6;
    int t = threadIdx.x;
    int tx = t & 15, ty = t >> 4;
    int lr = t & 63;            // row / key index for cooperative loads
    int dp = (t >> 6) << 4;     // dim chunk start: 0,16,32,48

    const float* qbase = qkv + (size_t)(q0 + lr) * (3 * C_DIM) + h * HD;
#pragma unroll
    for (int i = 0; i < 4; i++) {
        float4 v = *(const float4*)(qbase + dp + i * 4);
        Qs[dp + i * 4 + 0][lr] = v.x; Qs[dp + i * 4 + 1][lr] = v.y;
        Qs[dp + i * 4 + 2][lr] = v.z; Qs[dp + i * 4 + 3][lr] = v.w;
    }

    float acc[4][4] = {};
    float m_i[4] = {-1e30f, -1e30f, -1e30f, -1e30f};
    float l_i[4] = {};
    const float scale = 0.125f;   // 1/sqrt(64)
    int ntile = (q0 >> 6) + 1;

    for (int jt = 0; jt < ntile; jt++) {
        int j0 = jt << 6;
        const float* kbase = qkv + (size_t)(j0 + lr) * (3 * C_DIM) + C_DIM + h * HD;
        const float* vbase = qkv + (size_t)(j0 + lr) * (3 * C_DIM) + 2 * C_DIM + h * HD;
#pragma unroll
        for (int i = 0; i < 4; i++) {
            float4 kv = *(const float4*)(kbase + dp + i * 4);
            Ks[dp + i * 4 + 0][lr] = kv.x; Ks[dp + i * 4 + 1][lr] = kv.y;
            Ks[dp + i * 4 + 2][lr] = kv.z; Ks[dp + i * 4 + 3][lr] = kv.w;
            *(float4*)&Vs[lr][dp + i * 4] = *(const float4*)(vbase + dp + i * 4);
        }
        __syncthreads();

        float s[4][4] = {};
#pragma unroll
        for (int d = 0; d < 64; d++) {
            float4 qv = *(const float4*)&Qs[d][ty * 4];
            float4 kv = *(const float4*)&Ks[d][tx * 4];
            float qa[4] = {qv.x, qv.y, qv.z, qv.w};
            float kb[4] = {kv.x, kv.y, kv.z, kv.w};
#pragma unroll
            for (int i = 0; i < 4; i++)
#pragma unroll
                for (int j = 0; j < 4; j++)
                    s[i][j] = fmaf(qa[i], kb[j], s[i][j]);
        }

        bool diag = (jt == ntile - 1);
#pragma unroll
        for (int i = 0; i < 4; i++)
#pragma unroll
            for (int j = 0; j < 4; j++) {
                s[i][j] *= scale;
                if (diag && (tx * 4 + j) > (ty * 4 + i)) s[i][j] = -1e30f;
            }

#pragma unroll
        for (int i = 0; i < 4; i++) {
            float rmax = fmaxf(fmaxf(s[i][0], s[i][1]), fmaxf(s[i][2], s[i][3]));
#pragma unroll
            for (int off = 8; off; off >>= 1)
                rmax = fmaxf(rmax, __shfl_xor_sync(~0u, rmax, off, 16));
            float nm = fmaxf(m_i[i], rmax);
            float alpha = __expf(m_i[i] - nm);
            m_i[i] = nm;
            float rs = 0.f;
#pragma unroll
            for (int j = 0; j < 4; j++) { s[i][j] = __expf(s[i][j] - nm); rs += s[i][j]; }
#pragma unroll
            for (int off = 8; off; off >>= 1)
                rs += __shfl_xor_sync(~0u, rs, off, 16);
            l_i[i] = l_i[i] * alpha + rs;
#pragma unroll
            for (int j = 0; j < 4; j++) acc[i][j] *= alpha;
        }

        // stage P = softmax tile into smem as [key][row]
#pragma unroll
        for (int i = 0; i < 4; i++)
#pragma unroll
            for (int j = 0; j < 4; j++)
                Ps[tx * 4 + j][ty * 4 + i] = s[i][j];
        __syncthreads();

#pragma unroll
        for (int kk = 0; kk < 64; kk++) {
            float4 pv = *(const float4*)&Ps[kk][ty * 4];
            float4 vv = *(const float4*)&Vs[kk][tx * 4];
            float pa[4] = {pv.x, pv.y, pv.z, pv.w};
            float vb[4] = {vv.x, vv.y, vv.z, vv.w};
#pragma unroll
            for (int i = 0; i < 4; i++)
#pragma unroll
                for (int j = 0; j < 4; j++)
                    acc[i][j] = fmaf(pa[i], vb[j], acc[i][j]);
        }
        __syncthreads();
    }

#pragma unroll
    for (int i = 0; i < 4; i++) {
        float inv = 1.0f / l_i[i];
        float4 ov = make_float4(acc[i][0] * inv, acc[i][1] * inv,
                                acc[i][2] * inv, acc[i][3] * inv);
        *(float4*)(y + (size_t)(q0 + ty * 4 + i) * C_DIM + h * HD + tx * 4) = ov;
    }
}

// ---------------- silu(a) * b, elementwise, float4 ----------------
__global__ __launch_bounds__(256) void silu_mul_kernel(const float* __restrict__ a,
                                                       const float* __restrict__ b,
                                                       float* __restrict__ o, int n4) {
    int i = blockIdx.x * blockDim.x + threadIdx.x;
    if (i < n4) {
        float4 x = ((const float4*)a)[i];
        float4 g = ((const float4*)b)[i];
        float4 r;
        r.x = x.x / (1.f + __expf(-x.x)) * g.x;
        r.y = x.y / (1.f + __expf(-x.y)) * g.y;
        r.z = x.z / (1.f + __expf(-x.z)) * g.z;
        r.w = x.w / (1.f + __expf(-x.w)) * g.w;
        ((float4*)o)[i] = r;
    }
}

// ---------------- orchestration ----------------
extern "C" void kernel_launch(void* const* d_in, const int* in_sizes, int n_in,
                              void* d_out, int out_size) {
    const float* x      = (const float*)d_in[0];
    const float* anw    = (const float*)d_in[1];
    const float* fnw    = (const float*)d_in[2];
    const float* c_attn = (const float*)d_in[3];   // [3C, C]
    const float* c_proj = (const float*)d_in[4];   // [C, C]
    const float* w1     = (const float*)d_in[5];   // [Hf, C]
    const float* w2     = (const float*)d_in[6];   // [C, Hf]
    const float* w3     = (const float*)d_in[7];   // [Hf, C]
    float* out = (float*)d_out;

    float *xn, *qkv, *y, *x2, *xn2, *h1, *h3;
    cudaGetSymbolAddress((void**)&xn,  g_xn);
    cudaGetSymbolAddress((void**)&qkv, g_qkv);
    cudaGetSymbolAddress((void**)&y,   g_y);
    cudaGetSymbolAddress((void**)&x2,  g_x2);
    cudaGetSymbolAddress((void**)&xn2, g_xn2);
    cudaGetSymbolAddress((void**)&h1,  g_h1);
    cudaGetSymbolAddress((void**)&h3,  g_h3);

    cudaFuncSetAttribute(flash_attn_kernel,
                         cudaFuncAttributeMaxDynamicSharedMemorySize, ATTN_SMEM);

    // 1) xn = rmsnorm(x, attn_norm_w)
    rmsnorm_kernel<<<T_DIM, 256>>>(x, anw, xn);

    // 2) qkv = xn @ c_attn^T   [4096, 3072]
    {
        dim3 g(3 * C_DIM / 128, T_DIM / 128);
        gemm_tn<<<g, 256>>>(xn, c_attn, nullptr, qkv, T_DIM, 3 * C_DIM, C_DIM);
    }

    // 3) y = causal_attention(qkv)
    {
        dim3 g(T_DIM / 64, NH);
        flash_attn_kernel<<<g, 256, ATTN_SMEM>>>(qkv, y);
    }

    // 4) x2 = y @ c_proj^T + x
    {
        dim3 g(C_DIM / 128, T_DIM / 128);
        gemm_tn<<<g, 256>>>(y, c_proj, x, x2, T_DIM, C_DIM, C_DIM);
    }

    // 5) xn2 = rmsnorm(x2, ffn_norm_w)
    rmsnorm_kernel<<<T_DIM, 256>>>(x2, fnw, xn2);

    // 6) h1 = xn2 @ w1^T ; h3 = xn2 @ w3^T   [4096, 4096]
    {
        dim3 g(HF_DIM / 128, T_DIM / 128);
        gemm_tn<<<g, 256>>>(xn2, w1, nullptr, h1, T_DIM, HF_DIM, C_DIM);
        gemm_tn<<<g, 256>>>(xn2, w3, nullptr, h3, T_DIM, HF_DIM, C_DIM);
    }

    // 7) h1 = silu(h1) * h3
    {
        int n4 = T_DIM * HF_DIM / 4;
        silu_mul_kernel<<<(n4 + 255) / 256, 256>>>(h1, h3, h1, n4);
    }

    // 8) out = h1 @ w2^T + x2
    {
        dim3 g(C_DIM / 128, T_DIM / 128);
        gemm_tn<<<g, 256>>>(h1, w2, x2, out, T_DIM, C_DIM, HF_DIM);
    }
}

// round 3
// speedup vs baseline: 1.6733x; 1.6733x over previous
#include <cuda_runtime.h>
#include <cuda_bf16.h>
#include <cstdint>
#include <math.h>

#define T_DIM 4096
#define C_DIM 1024
#define HF_DIM 4096
#define NH 16
#define HD 64

// ---------------- scratch (module-static, no runtime allocation) ----------------
__device__ float g_xn [T_DIM * C_DIM];
__device__ float g_qkv[T_DIM * 3 * C_DIM];
__device__ float g_y  [T_DIM * C_DIM];
__device__ float g_x2 [T_DIM * C_DIM];
__device__ float g_xn2[T_DIM * C_DIM];
__device__ float g_h1 [T_DIM * HF_DIM];
__device__ float g_h3 [T_DIM * HF_DIM];

// ================= bf16-split tensor-core GEMM =================
// C[M,N] = A[M,K] @ B[N,K]^T (+ R), fp32 in/out.
// Each fp32 split as hi+lo bf16; 3 MMAs recover ~18 mantissa bits.
// CTA tile 128x128, BK=32, 8 warps (2M x 4N), warp tile 64x32.
// smem pitch 40 bf16 => conflict-free fragment loads.

#define BM 128
#define BN 128
#define BK 32
#define PITCH 40
#define ARR_BYTES (128 * PITCH * 2)       // 10240 per array
#define STAGE_BYTES (4 * ARR_BYTES)       // Ah, Al, Bh, Bl = 40960
#define GEMM_SMEM (2 * STAGE_BYTES)       // 81920

static __device__ __forceinline__ void mma_bf16(float* c, const uint32_t* a,
                                                const uint32_t* b) {
    asm volatile(
        "mma.sync.aligned.m16n8k16.row.col.f32.bf16.bf16.f32 "
        "{%0,%1,%2,%3}, {%4,%5,%6,%7}, {%8,%9}, {%0,%1,%2,%3};"
        : "+f"(c[0]), "+f"(c[1]), "+f"(c[2]), "+f"(c[3])
        : "r"(a[0]), "r"(a[1]), "r"(a[2]), "r"(a[3]), "r"(b[0]), "r"(b[1]));
}

static __device__ __forceinline__ uint32_t pack_bf2(float x, float y) {
    __nv_bfloat162 h;
    h.x = __float2bfloat16(x);
    h.y = __float2bfloat16(y);
    return *(uint32_t*)&h;
}

__global__ __launch_bounds__(256) void gemm_mma(const float* __restrict__ A,
                                                const float* __restrict__ B,
                                                const float* __restrict__ R,
                                                float* __restrict__ C,
                                                int M, int N, int K) {
    extern __shared__ char sm[];
    const int t = threadIdx.x;
    const int w = t >> 5;
    const int lane = t & 31;
    const int g = lane >> 2;      // group id 0..7
    const int tig = lane & 3;     // thread-in-group
    const int wm = w >> 2;        // 0..1 (M)
    const int wn = w & 3;         // 0..3 (N)

    const int m0 = blockIdx.y * BM;
    const int n0 = blockIdx.x * BN;
    const int nk = K / BK;

    const float* Abase = A + (size_t)m0 * K;
    const float* Bbase = B + (size_t)n0 * K;

    float acc[4][4][4] = {};      // [mi][ni][4]

    for (int i = 0; i < nk; i++) {
        const int st = i & 1;
        __nv_bfloat16* Ah = (__nv_bfloat16*)(sm + st * STAGE_BYTES);
        __nv_bfloat16* Al = (__nv_bfloat16*)(sm + st * STAGE_BYTES + ARR_BYTES);
        __nv_bfloat16* Bh = (__nv_bfloat16*)(sm + st * STAGE_BYTES + 2 * ARR_BYTES);
        __nv_bfloat16* Bl = (__nv_bfloat16*)(sm + st * STAGE_BYTES + 3 * ARR_BYTES);
        const int k0 = i * BK;

        // ---- global load + split: A and B chunks are 128 rows x 32 floats ----
#pragma unroll
        for (int it = 0; it < 4; it++) {
            int idx = t + (it << 8);
            int row = idx >> 3, c4 = idx & 7;
            float4 v = *(const float4*)(Abase + (size_t)row * K + k0 + (c4 << 2));
            uint32_t h01 = pack_bf2(v.x, v.y), h23 = pack_bf2(v.z, v.w);
            float lx = v.x - __bfloat162float(((__nv_bfloat162*)&h01)->x);
            float ly = v.y - __bfloat162float(((__nv_bfloat162*)&h01)->y);
            float lz = v.z - __bfloat162float(((__nv_bfloat162*)&h23)->x);
            float lw = v.w - __bfloat162float(((__nv_bfloat162*)&h23)->y);
            uint32_t l01 = pack_bf2(lx, ly), l23 = pack_bf2(lz, lw);
            int off = row * PITCH + (c4 << 2);
            *(uint2*)(Ah + off) = make_uint2(h01, h23);
            *(uint2*)(Al + off) = make_uint2(l01, l23);
        }
#pragma unroll
        for (int it = 0; it < 4; it++) {
            int idx = t + (it << 8);
            int row = idx >> 3, c4 = idx & 7;
            float4 v = *(const float4*)(Bbase + (size_t)row * K + k0 + (c4 << 2));
            uint32_t h01 = pack_bf2(v.x, v.y), h23 = pack_bf2(v.z, v.w);
            float lx = v.x - __bfloat162float(((__nv_bfloat162*)&h01)->x);
            float ly = v.y - __bfloat162float(((__nv_bfloat162*)&h01)->y);
            float lz = v.z - __bfloat162float(((__nv_bfloat162*)&h23)->x);
            float lw = v.w - __bfloat162float(((__nv_bfloat162*)&h23)->y);
            uint32_t l01 = pack_bf2(lx, ly), l23 = pack_bf2(lz, lw);
            int off = row * PITCH + (c4 << 2);
            *(uint2*)(Bh + off) = make_uint2(h01, h23);
            *(uint2*)(Bl + off) = make_uint2(l01, l23);
        }
        __syncthreads();

        // ---- compute: 2 k-steps of m16n8k16 ----
#pragma unroll
        for (int kk = 0; kk < BK; kk += 16) {
            uint32_t ahi[4][4], alo[4][4], bhi[4][2], blo[4][2];
#pragma unroll
            for (int mi = 0; mi < 4; mi++) {
                int r = wm * 64 + mi * 16 + g;
                int c = kk + tig * 2;
                ahi[mi][0] = *(const uint32_t*)(Ah + r * PITCH + c);
                ahi[mi][1] = *(const uint32_t*)(Ah + (r + 8) * PITCH + c);
                ahi[mi][2] = *(const uint32_t*)(Ah + r * PITCH + c + 8);
                ahi[mi][3] = *(const uint32_t*)(Ah + (r + 8) * PITCH + c + 8);
                alo[mi][0] = *(const uint32_t*)(Al + r * PITCH + c);
                alo[mi][1] = *(const uint32_t*)(Al + (r + 8) * PITCH + c);
                alo[mi][2] = *(const uint32_t*)(Al + r * PITCH + c + 8);
                alo[mi][3] = *(const uint32_t*)(Al + (r + 8) * PITCH + c + 8);
            }
#pragma unroll
            for (int ni = 0; ni < 4; ni++) {
                int n = wn * 32 + ni * 8 + g;
                int c = kk + tig * 2;
                bhi[ni][0] = *(const uint32_t*)(Bh + n * PITCH + c);
                bhi[ni][1] = *(const uint32_t*)(Bh + n * PITCH + c + 8);
                blo[ni][0] = *(const uint32_t*)(Bl + n * PITCH + c);
                blo[ni][1] = *(const uint32_t*)(Bl + n * PITCH + c + 8);
            }
#pragma unroll
            for (int mi = 0; mi < 4; mi++)
#pragma unroll
                for (int ni = 0; ni < 4; ni++) {
                    mma_bf16(acc[mi][ni], ahi[mi], bhi[ni]);
                    mma_bf16(acc[mi][ni], ahi[mi], blo[ni]);
                    mma_bf16(acc[mi][ni], alo[mi], bhi[ni]);
                }
        }
        __syncthreads();
    }

    // ---- epilogue ----
#pragma unroll
    for (int mi = 0; mi < 4; mi++) {
        int r = m0 + wm * 64 + mi * 16 + g;
#pragma unroll
        for (int ni = 0; ni < 4; ni++) {
            int col = n0 + wn * 32 + ni * 8 + tig * 2;
            float2 v0 = make_float2(acc[mi][ni][0], acc[mi][ni][1]);
            float2 v1 = make_float2(acc[mi][ni][2], acc[mi][ni][3]);
            size_t o0 = (size_t)r * N + col;
            size_t o1 = (size_t)(r + 8) * N + col;
            if (R) {
                float2 r0 = *(const float2*)(R + o0);
                float2 r1 = *(const float2*)(R + o1);
                v0.x += r0.x; v0.y += r0.y;
                v1.x += r1.x; v1.y += r1.y;
            }
            *(float2*)(C + o0) = v0;
            *(float2*)(C + o1) = v1;
        }
    }
}

// ---------------- rmsnorm: one block per row, 256 threads, C=1024 ----------------
__global__ __launch_bounds__(256) void rmsnorm_kernel(const float* __restrict__ x,
                                                      const float* __restrict__ w,
                                                      float* __restrict__ o) {
    int row = blockIdx.x;
    int t = threadIdx.x;
    const float4* xr = (const float4*)(x + (size_t)row * C_DIM);
    float4 v = xr[t];
    float ss = v.x * v.x + v.y * v.y + v.z * v.z + v.w * v.w;
    __shared__ float red[8];
#pragma unroll
    for (int off = 16; off; off >>= 1) ss += __shfl_xor_sync(~0u, ss, off);
    if ((t & 31) == 0) red[t >> 5] = ss;
    __syncthreads();
    if (t < 32) {
        float s2 = (t < 8) ? red[t] : 0.f;
#pragma unroll
        for (int off = 4; off; off >>= 1) s2 += __shfl_xor_sync(~0u, s2, off);
        if (t == 0) red[0] = s2;
    }
    __syncthreads();
    float rn = rsqrtf(red[0] * (1.0f / C_DIM) + 1e-6f);
    float4 wv = ((const float4*)w)[t];
    float4 ov = make_float4(v.x * rn * wv.x, v.y * rn * wv.y, v.z * rn * wv.z, v.w * rn * wv.w);
    ((float4*)(o + (size_t)row * C_DIM))[t] = ov;
}

// ---------------- causal flash attention, fp32, hd=64, 64x64 tiles ----------------
#define APITCH 68
#define ATTN_SMEM (4 * 64 * APITCH * 4)

__global__ __launch_bounds__(256) void flash_attn_kernel(const float* __restrict__ qkv,
                                                         float* __restrict__ y) {
    extern __shared__ float smf[];
    float (*Qs)[APITCH] = (float (*)[APITCH])smf;
    float (*Ks)[APITCH] = (float (*)[APITCH])(smf + 64 * APITCH);
    float (*Vs)[APITCH] = (float (*)[APITCH])(smf + 2 * 64 * APITCH);
    float (*Ps)[APITCH] = (float (*)[APITCH])(smf + 3 * 64 * APITCH);
    int h = blockIdx.y;
    int q0 = blockIdx.x << 6;
    int t = threadIdx.x;
    int tx = t & 15, ty = t >> 4;
    int lr = t & 63;
    int dp = (t >> 6) << 4;

    const float* qbase = qkv + (size_t)(q0 + lr) * (3 * C_DIM) + h * HD;
#pragma unroll
    for (int i = 0; i < 4; i++) {
        float4 v = *(const float4*)(qbase + dp + i * 4);
        Qs[dp + i * 4 + 0][lr] = v.x; Qs[dp + i * 4 + 1][lr] = v.y;
        Qs[dp + i * 4 + 2][lr] = v.z; Qs[dp + i * 4 + 3][lr] = v.w;
    }

    float acc[4][4] = {};
    float m_i[4] = {-1e30f, -1e30f, -1e30f, -1e30f};
    float l_i[4] = {};
    const float scale = 0.125f;
    int ntile = (q0 >> 6) + 1;

    for (int jt = 0; jt < ntile; jt++) {
        int j0 = jt << 6;
        const float* kbase = qkv + (size_t)(j0 + lr) * (3 * C_DIM) + C_DIM + h * HD;
        const float* vbase = qkv + (size_t)(j0 + lr) * (3 * C_DIM) + 2 * C_DIM + h * HD;
#pragma unroll
        for (int i = 0; i < 4; i++) {
            float4 kv = *(const float4*)(kbase + dp + i * 4);
            Ks[dp + i * 4 + 0][lr] = kv.x; Ks[dp + i * 4 + 1][lr] = kv.y;
            Ks[dp + i * 4 + 2][lr] = kv.z; Ks[dp + i * 4 + 3][lr] = kv.w;
            *(float4*)&Vs[lr][dp + i * 4] = *(const float4*)(vbase + dp + i * 4);
        }
        __syncthreads();

        float s[4][4] = {};
#pragma unroll
        for (int d = 0; d < 64; d++) {
            float4 qv = *(const float4*)&Qs[d][ty * 4];
            float4 kv = *(const float4*)&Ks[d][tx * 4];
            float qa[4] = {qv.x, qv.y, qv.z, qv.w};
            float kb[4] = {kv.x, kv.y, kv.z, kv.w};
#pragma unroll
            for (int i = 0; i < 4; i++)
#pragma unroll
                for (int j = 0; j < 4; j++)
                    s[i][j] = fmaf(qa[i], kb[j], s[i][j]);
        }

        bool diag = (jt == ntile - 1);
#pragma unroll
        for (int i = 0; i < 4; i++)
#pragma unroll
            for (int j = 0; j < 4; j++) {
                s[i][j] *= scale;
                if (diag && (tx * 4 + j) > (ty * 4 + i)) s[i][j] = -1e30f;
            }

#pragma unroll
        for (int i = 0; i < 4; i++) {
            float rmax = fmaxf(fmaxf(s[i][0], s[i][1]), fmaxf(s[i][2], s[i][3]));
#pragma unroll
            for (int off = 8; off; off >>= 1)
                rmax = fmaxf(rmax, __shfl_xor_sync(~0u, rmax, off, 16));
            float nm = fmaxf(m_i[i], rmax);
            float alpha = __expf(m_i[i] - nm);
            m_i[i] = nm;
            float rs = 0.f;
#pragma unroll
            for (int j = 0; j < 4; j++) { s[i][j] = __expf(s[i][j] - nm); rs += s[i][j]; }
#pragma unroll
            for (int off = 8; off; off >>= 1)
                rs += __shfl_xor_sync(~0u, rs, off, 16);
            l_i[i] = l_i[i] * alpha + rs;
#pragma unroll
            for (int j = 0; j < 4; j++) acc[i][j] *= alpha;
        }

#pragma unroll
        for (int i = 0; i < 4; i++)
#pragma unroll
            for (int j = 0; j < 4; j++)
                Ps[tx * 4 + j][ty * 4 + i] = s[i][j];
        __syncthreads();

#pragma unroll
        for (int kk = 0; kk < 64; kk++) {
            float4 pv = *(const float4*)&Ps[kk][ty * 4];
            float4 vv = *(const float4*)&Vs[kk][tx * 4];
            float pa[4] = {pv.x, pv.y, pv.z, pv.w};
            float vb[4] = {vv.x, vv.y, vv.z, vv.w};
#pragma unroll
            for (int i = 0; i < 4; i++)
#pragma unroll
                for (int j = 0; j < 4; j++)
                    acc[i][j] = fmaf(pa[i], vb[j], acc[i][j]);
        }
        __syncthreads();
    }

#pragma unroll
    for (int i = 0; i < 4; i++) {
        float inv = 1.0f / l_i[i];
        float4 ov = make_float4(acc[i][0] * inv, acc[i][1] * inv,
                                acc[i][2] * inv, acc[i][3] * inv);
        *(float4*)(y + (size_t)(q0 + ty * 4 + i) * C_DIM + h * HD + tx * 4) = ov;
    }
}

// ---------------- silu(a) * b, elementwise, float4 ----------------
__global__ __launch_bounds__(256) void silu_mul_kernel(const float* __restrict__ a,
                                                       const float* __restrict__ b,
                                                       float* __restrict__ o, int n4) {
    int i = blockIdx.x * blockDim.x + threadIdx.x;
    if (i < n4) {
        float4 x = ((const float4*)a)[i];
        float4 g = ((const float4*)b)[i];
        float4 r;
        r.x = x.x / (1.f + __expf(-x.x)) * g.x;
        r.y = x.y / (1.f + __expf(-x.y)) * g.y;
        r.z = x.z / (1.f + __expf(-x.z)) * g.z;
        r.w = x.w / (1.f + __expf(-x.w)) * g.w;
        ((float4*)o)[i] = r;
    }
}

// ---------------- orchestration ----------------
extern "C" void kernel_launch(void* const* d_in, const int* in_sizes, int n_in,
                              void* d_out, int out_size) {
    const float* x      = (const float*)d_in[0];
    const float* anw    = (const float*)d_in[1];
    const float* fnw    = (const float*)d_in[2];
    const float* c_attn = (const float*)d_in[3];
    const float* c_proj = (const float*)d_in[4];
    const float* w1     = (const float*)d_in[5];
    const float* w2     = (const float*)d_in[6];
    const float* w3     = (const float*)d_in[7];
    float* out = (float*)d_out;

    float *xn, *qkv, *y, *x2, *xn2, *h1, *h3;
    cudaGetSymbolAddress((void**)&xn,  g_xn);
    cudaGetSymbolAddress((void**)&qkv, g_qkv);
    cudaGetSymbolAddress((void**)&y,   g_y);
    cudaGetSymbolAddress((void**)&x2,  g_x2);
    cudaGetSymbolAddress((void**)&xn2, g_xn2);
    cudaGetSymbolAddress((void**)&h1,  g_h1);
    cudaGetSymbolAddress((void**)&h3,  g_h3);

    cudaFuncSetAttribute(flash_attn_kernel,
                         cudaFuncAttributeMaxDynamicSharedMemorySize, ATTN_SMEM);
    cudaFuncSetAttribute(gemm_mma,
                         cudaFuncAttributeMaxDynamicSharedMemorySize, GEMM_SMEM);

    // 1) xn = rmsnorm(x, attn_norm_w)
    rmsnorm_kernel<<<T_DIM, 256>>>(x, anw, xn);

    // 2) qkv = xn @ c_attn^T   [4096, 3072]
    gemm_mma<<<dim3(3 * C_DIM / BN, T_DIM / BM), 256, GEMM_SMEM>>>(
        xn, c_attn, nullptr, qkv, T_DIM, 3 * C_DIM, C_DIM);

    // 3) y = causal_attention(qkv)
    flash_attn_kernel<<<dim3(T_DIM / 64, NH), 256, ATTN_SMEM>>>(qkv, y);

    // 4) x2 = y @ c_proj^T + x
    gemm_mma<<<dim3(C_DIM / BN, T_DIM / BM), 256, GEMM_SMEM>>>(
        y, c_proj, x, x2, T_DIM, C_DIM, C_DIM);

    // 5) xn2 = rmsnorm(x2, ffn_norm_w)
    rmsnorm_kernel<<<T_DIM, 256>>>(x2, fnw, xn2);

    // 6) h1 = xn2 @ w1^T ; h3 = xn2 @ w3^T   [4096, 4096]
    gemm_mma<<<dim3(HF_DIM / BN, T_DIM / BM), 256, GEMM_SMEM>>>(
        xn2, w1, nullptr, h1, T_DIM, HF_DIM, C_DIM);
    gemm_mma<<<dim3(HF_DIM / BN, T_DIM / BM), 256, GEMM_SMEM>>>(
        xn2, w3, nullptr, h3, T_DIM, HF_DIM, C_DIM);

    // 7) h1 = silu(h1) * h3
    {
        int n4 = T_DIM * HF_DIM / 4;
        silu_mul_kernel<<<(n4 + 255) / 256, 256>>>(h1, h3, h1, n4);
    }

    // 8) out = h1 @ w2^T + x2
    gemm_mma<<<dim3(C_DIM / BN, T_DIM / BM), 256, GEMM_SMEM>>>(
        h1, w2, x2, out, T_DIM, C_DIM, HF_DIM);
}

// round 4
// speedup vs baseline: 2.4077x; 1.4389x over previous
#include <cuda_runtime.h>
#include <cuda_bf16.h>
#include <cstdint>
#include <math.h>

#define T_DIM 4096
#define C_DIM 1024
#define HF_DIM 4096
#define NH 16
#define HD 64

// ---------------- scratch (module-static, no runtime allocation) ----------------
__device__ float g_xn [T_DIM * C_DIM];
__device__ float g_qkv[T_DIM * 3 * C_DIM];
__device__ float g_y  [T_DIM * C_DIM];
__device__ float g_x2 [T_DIM * C_DIM];
__device__ float g_xn2[T_DIM * C_DIM];
__device__ float g_h1 [T_DIM * HF_DIM];
__device__ float g_h3 [T_DIM * HF_DIM];

// ================= common MMA helpers =================
static __device__ __forceinline__ void mma_bf16(float* c, const uint32_t* a,
                                                const uint32_t* b) {
    asm volatile(
        "mma.sync.aligned.m16n8k16.row.col.f32.bf16.bf16.f32 "
        "{%0,%1,%2,%3}, {%4,%5,%6,%7}, {%8,%9}, {%0,%1,%2,%3};"
        : "+f"(c[0]), "+f"(c[1]), "+f"(c[2]), "+f"(c[3])
        : "r"(a[0]), "r"(a[1]), "r"(a[2]), "r"(a[3]), "r"(b[0]), "r"(b[1]));
}
static __device__ __forceinline__ uint32_t pack_bf2(float x, float y) {
    __nv_bfloat162 h;
    h.x = __float2bfloat16(x);
    h.y = __float2bfloat16(y);
    return *(uint32_t*)&h;
}
static __device__ __forceinline__ float bf_lo_res(float v, uint32_t packed, int hi) {
    __nv_bfloat162* p = (__nv_bfloat162*)&packed;
    return v - __bfloat162float(hi ? p->y : p->x);
}

// ================= bf16-split tensor-core GEMM (unchanged from R3) =================
#define BM 128
#define BN 128
#define BK 32
#define PITCH 40
#define ARR_BYTES (128 * PITCH * 2)
#define STAGE_BYTES (4 * ARR_BYTES)
#define GEMM_SMEM (2 * STAGE_BYTES)

__global__ __launch_bounds__(256) void gemm_mma(const float* __restrict__ A,
                                                const float* __restrict__ B,
                                                const float* __restrict__ R,
                                                float* __restrict__ C,
                                                int M, int N, int K) {
    extern __shared__ char sm[];
    const int t = threadIdx.x;
    const int w = t >> 5;
    const int lane = t & 31;
    const int g = lane >> 2;
    const int tig = lane & 3;
    const int wm = w >> 2;
    const int wn = w & 3;

    const int m0 = blockIdx.y * BM;
    const int n0 = blockIdx.x * BN;
    const int nk = K / BK;

    const float* Abase = A + (size_t)m0 * K;
    const float* Bbase = B + (size_t)n0 * K;

    float acc[4][4][4] = {};

    for (int i = 0; i < nk; i++) {
        const int st = i & 1;
        __nv_bfloat16* Ah = (__nv_bfloat16*)(sm + st * STAGE_BYTES);
        __nv_bfloat16* Al = (__nv_bfloat16*)(sm + st * STAGE_BYTES + ARR_BYTES);
        __nv_bfloat16* Bh = (__nv_bfloat16*)(sm + st * STAGE_BYTES + 2 * ARR_BYTES);
        __nv_bfloat16* Bl = (__nv_bfloat16*)(sm + st * STAGE_BYTES + 3 * ARR_BYTES);
        const int k0 = i * BK;

#pragma unroll
        for (int it = 0; it < 4; it++) {
            int idx = t + (it << 8);
            int row = idx >> 3, c4 = idx & 7;
            float4 v = *(const float4*)(Abase + (size_t)row * K + k0 + (c4 << 2));
            uint32_t h01 = pack_bf2(v.x, v.y), h23 = pack_bf2(v.z, v.w);
            uint32_t l01 = pack_bf2(bf_lo_res(v.x, h01, 0), bf_lo_res(v.y, h01, 1));
            uint32_t l23 = pack_bf2(bf_lo_res(v.z, h23, 0), bf_lo_res(v.w, h23, 1));
            int off = row * PITCH + (c4 << 2);
            *(uint2*)(Ah + off) = make_uint2(h01, h23);
            *(uint2*)(Al + off) = make_uint2(l01, l23);
        }
#pragma unroll
        for (int it = 0; it < 4; it++) {
            int idx = t + (it << 8);
            int row = idx >> 3, c4 = idx & 7;
            float4 v = *(const float4*)(Bbase + (size_t)row * K + k0 + (c4 << 2));
            uint32_t h01 = pack_bf2(v.x, v.y), h23 = pack_bf2(v.z, v.w);
            uint32_t l01 = pack_bf2(bf_lo_res(v.x, h01, 0), bf_lo_res(v.y, h01, 1));
            uint32_t l23 = pack_bf2(bf_lo_res(v.z, h23, 0), bf_lo_res(v.w, h23, 1));
            int off = row * PITCH + (c4 << 2);
            *(uint2*)(Bh + off) = make_uint2(h01, h23);
            *(uint2*)(Bl + off) = make_uint2(l01, l23);
        }
        __syncthreads();

#pragma unroll
        for (int kk = 0; kk < BK; kk += 16) {
            uint32_t ahi[4][4], alo[4][4], bhi[4][2], blo[4][2];
#pragma unroll
            for (int mi = 0; mi < 4; mi++) {
                int r = wm * 64 + mi * 16 + g;
                int c = kk + tig * 2;
                ahi[mi][0] = *(const uint32_t*)(Ah + r * PITCH + c);
                ahi[mi][1] = *(const uint32_t*)(Ah + (r + 8) * PITCH + c);
                ahi[mi][2] = *(const uint32_t*)(Ah + r * PITCH + c + 8);
                ahi[mi][3] = *(const uint32_t*)(Ah + (r + 8) * PITCH + c + 8);
                alo[mi][0] = *(const uint32_t*)(Al + r * PITCH + c);
                alo[mi][1] = *(const uint32_t*)(Al + (r + 8) * PITCH + c);
                alo[mi][2] = *(const uint32_t*)(Al + r * PITCH + c + 8);
                alo[mi][3] = *(const uint32_t*)(Al + (r + 8) * PITCH + c + 8);
            }
#pragma unroll
            for (int ni = 0; ni < 4; ni++) {
                int n = wn * 32 + ni * 8 + g;
                int c = kk + tig * 2;
                bhi[ni][0] = *(const uint32_t*)(Bh + n * PITCH + c);
                bhi[ni][1] = *(const uint32_t*)(Bh + n * PITCH + c + 8);
                blo[ni][0] = *(const uint32_t*)(Bl + n * PITCH + c);
                blo[ni][1] = *(const uint32_t*)(Bl + n * PITCH + c + 8);
            }
#pragma unroll
            for (int mi = 0; mi < 4; mi++)
#pragma unroll
                for (int ni = 0; ni < 4; ni++) {
                    mma_bf16(acc[mi][ni], ahi[mi], bhi[ni]);
                    mma_bf16(acc[mi][ni], ahi[mi], blo[ni]);
                    mma_bf16(acc[mi][ni], alo[mi], bhi[ni]);
                }
        }
        __syncthreads();
    }

#pragma unroll
    for (int mi = 0; mi < 4; mi++) {
        int r = m0 + wm * 64 + mi * 16 + g;
#pragma unroll
        for (int ni = 0; ni < 4; ni++) {
            int col = n0 + wn * 32 + ni * 8 + tig * 2;
            float2 v0 = make_float2(acc[mi][ni][0], acc[mi][ni][1]);
            float2 v1 = make_float2(acc[mi][ni][2], acc[mi][ni][3]);
            size_t o0 = (size_t)r * N + col;
            size_t o1 = (size_t)(r + 8) * N + col;
            if (R) {
                float2 r0 = *(const float2*)(R + o0);
                float2 r1 = *(const float2*)(R + o1);
                v0.x += r0.x; v0.y += r0.y;
                v1.x += r1.x; v1.y += r1.y;
            }
            *(float2*)(C + o0) = v0;
            *(float2*)(C + o1) = v1;
        }
    }
}

// ================= tensor-core flash attention (split bf16) =================
// CTA: 1 head x 128 q rows. 8 warps x 16 rows. KV tiles of 64 keys.
// smem (bf16 units, pitch 72): Qh 128x72 | Ql | Kh 64x72 | Kl | Vh(T) 64x72 | Vl(T)
#define AP 72
#define SQH 0
#define SQL (128 * AP)
#define SKH (256 * AP)
#define SKL (320 * AP)
#define SVH (384 * AP)
#define SVL (448 * AP)
#define ATTN_SMEM (512 * AP * 2)   // 73728 bytes

__global__ __launch_bounds__(256) void attn_mma(const float* __restrict__ qkv,
                                                float* __restrict__ y) {
    extern __shared__ __nv_bfloat16 asm_[];
    const int h = blockIdx.y;
    const int q0 = blockIdx.x << 7;
    const int t = threadIdx.x;
    const int w = t >> 5;
    const int lane = t & 31;
    const int g = lane >> 2;
    const int tig = lane & 3;

    // ---- load Q tile (scaled by 1/8), split hi/lo ----
#pragma unroll
    for (int it = 0; it < 8; it++) {
        int idx = t + (it << 8);
        int row = idx >> 4, c4 = idx & 15;
        float4 v = *(const float4*)(qkv + (size_t)(q0 + row) * (3 * C_DIM) + h * HD + (c4 << 2));
        v.x *= 0.125f; v.y *= 0.125f; v.z *= 0.125f; v.w *= 0.125f;
        uint32_t h01 = pack_bf2(v.x, v.y), h23 = pack_bf2(v.z, v.w);
        uint32_t l01 = pack_bf2(bf_lo_res(v.x, h01, 0), bf_lo_res(v.y, h01, 1));
        uint32_t l23 = pack_bf2(bf_lo_res(v.z, h23, 0), bf_lo_res(v.w, h23, 1));
        int off = row * AP + (c4 << 2);
        *(uint2*)(asm_ + SQH + off) = make_uint2(h01, h23);
        *(uint2*)(asm_ + SQL + off) = make_uint2(l01, l23);
    }
    __syncthreads();

    // ---- Q fragments to registers ----
    uint32_t qh[4][4], ql[4][4];
    {
        int r = w * 16 + g;
#pragma unroll
        for (int ks = 0; ks < 4; ks++) {
            int c = ks * 16 + tig * 2;
            qh[ks][0] = *(const uint32_t*)(asm_ + SQH + r * AP + c);
            qh[ks][1] = *(const uint32_t*)(asm_ + SQH + (r + 8) * AP + c);
            qh[ks][2] = *(const uint32_t*)(asm_ + SQH + r * AP + c + 8);
            qh[ks][3] = *(const uint32_t*)(asm_ + SQH + (r + 8) * AP + c + 8);
            ql[ks][0] = *(const uint32_t*)(asm_ + SQL + r * AP + c);
            ql[ks][1] = *(const uint32_t*)(asm_ + SQL + (r + 8) * AP + c);
            ql[ks][2] = *(const uint32_t*)(asm_ + SQL + r * AP + c + 8);
            ql[ks][3] = *(const uint32_t*)(asm_ + SQL + (r + 8) * AP + c + 8);
        }
    }

    float o[8][4] = {};
    float m0 = -1e30f, m1 = -1e30f, l0 = 0.f, l1 = 0.f;
    const int ntile = (q0 >> 6) + 2;
    const int r0 = q0 + w * 16 + g;   // global row of c0/c1
    const int r1 = r0 + 8;            // global row of c2/c3

    for (int jt = 0; jt < ntile; jt++) {
        const int j0 = jt << 6;
        // ---- load K tile (hi/lo) ----
#pragma unroll
        for (int it = 0; it < 4; it++) {
            int idx = t + (it << 8);
            int row = idx >> 4, c4 = idx & 15;
            float4 v = *(const float4*)(qkv + (size_t)(j0 + row) * (3 * C_DIM) + C_DIM + h * HD + (c4 << 2));
            uint32_t h01 = pack_bf2(v.x, v.y), h23 = pack_bf2(v.z, v.w);
            uint32_t l01 = pack_bf2(bf_lo_res(v.x, h01, 0), bf_lo_res(v.y, h01, 1));
            uint32_t l23 = pack_bf2(bf_lo_res(v.z, h23, 0), bf_lo_res(v.w, h23, 1));
            int off = row * AP + (c4 << 2);
            *(uint2*)(asm_ + SKH + off) = make_uint2(h01, h23);
            *(uint2*)(asm_ + SKL + off) = make_uint2(l01, l23);
        }
        // ---- load V tile transposed [dim][key] (hi/lo) ----
#pragma unroll
        for (int it = 0; it < 4; it++) {
            int idx = t + (it << 8);
            int row = idx >> 4, c4 = idx & 15;
            float4 v = *(const float4*)(qkv + (size_t)(j0 + row) * (3 * C_DIM) + 2 * C_DIM + h * HD + (c4 << 2));
            float vv[4] = {v.x, v.y, v.z, v.w};
#pragma unroll
            for (int i = 0; i < 4; i++) {
                int d = (c4 << 2) + i;
                __nv_bfloat16 hb = __float2bfloat16(vv[i]);
                asm_[SVH + d * AP + row] = hb;
                asm_[SVL + d * AP + row] = __float2bfloat16(vv[i] - __bfloat162float(hb));
            }
        }
        __syncthreads();

        // ---- S = Q K^T (3 split MMAs) ----
        float s[8][4];
#pragma unroll
        for (int nb = 0; nb < 8; nb++) {
            s[nb][0] = 0.f; s[nb][1] = 0.f; s[nb][2] = 0.f; s[nb][3] = 0.f;
            int n = nb * 8 + g;
#pragma unroll
            for (int ks = 0; ks < 4; ks++) {
                int c = ks * 16 + tig * 2;
                uint32_t bh[2], bl[2];
                bh[0] = *(const uint32_t*)(asm_ + SKH + n * AP + c);
                bh[1] = *(const uint32_t*)(asm_ + SKH + n * AP + c + 8);
                bl[0] = *(const uint32_t*)(asm_ + SKL + n * AP + c);
                bl[1] = *(const uint32_t*)(asm_ + SKL + n * AP + c + 8);
                mma_bf16(s[nb], qh[ks], bh);
                mma_bf16(s[nb], qh[ks], bl);
                mma_bf16(s[nb], ql[ks], bh);
            }
        }

        // ---- causal mask (only last two tiles can cross the diagonal) ----
        if (jt >= ntile - 2) {
#pragma unroll
            for (int nb = 0; nb < 8; nb++) {
                int c0 = j0 + nb * 8 + tig * 2;
                if (c0 > r0)     s[nb][0] = -1e30f;
                if (c0 + 1 > r0) s[nb][1] = -1e30f;
                if (c0 > r1)     s[nb][2] = -1e30f;
                if (c0 + 1 > r1) s[nb][3] = -1e30f;
            }
        }

        // ---- online softmax ----
        float tm0 = -1e30f, tm1 = -1e30f;
#pragma unroll
        for (int nb = 0; nb < 8; nb++) {
            tm0 = fmaxf(tm0, fmaxf(s[nb][0], s[nb][1]));
            tm1 = fmaxf(tm1, fmaxf(s[nb][2], s[nb][3]));
        }
        tm0 = fmaxf(tm0, __shfl_xor_sync(~0u, tm0, 1));
        tm0 = fmaxf(tm0, __shfl_xor_sync(~0u, tm0, 2));
        tm1 = fmaxf(tm1, __shfl_xor_sync(~0u, tm1, 1));
        tm1 = fmaxf(tm1, __shfl_xor_sync(~0u, tm1, 2));
        float nm0 = fmaxf(m0, tm0), nm1 = fmaxf(m1, tm1);
        float a0 = __expf(m0 - nm0), a1 = __expf(m1 - nm1);
        m0 = nm0; m1 = nm1;
        float rs0 = 0.f, rs1 = 0.f;
#pragma unroll
        for (int nb = 0; nb < 8; nb++) {
            s[nb][0] = __expf(s[nb][0] - nm0);
            s[nb][1] = __expf(s[nb][1] - nm0);
            s[nb][2] = __expf(s[nb][2] - nm1);
            s[nb][3] = __expf(s[nb][3] - nm1);
            rs0 += s[nb][0] + s[nb][1];
            rs1 += s[nb][2] + s[nb][3];
        }
        rs0 += __shfl_xor_sync(~0u, rs0, 1);
        rs0 += __shfl_xor_sync(~0u, rs0, 2);
        rs1 += __shfl_xor_sync(~0u, rs1, 1);
        rs1 += __shfl_xor_sync(~0u, rs1, 2);
        l0 = l0 * a0 + rs0;
        l1 = l1 * a1 + rs1;
#pragma unroll
        for (int nd = 0; nd < 8; nd++) {
            o[nd][0] *= a0; o[nd][1] *= a0; o[nd][2] *= a1; o[nd][3] *= a1;
        }

        // ---- O += P V  (P fragments built register-locally from S) ----
#pragma unroll
        for (int kb = 0; kb < 4; kb++) {
            uint32_t ph[4], pl[4];
            {
                float* sa = s[2 * kb];
                float* sb = s[2 * kb + 1];
                ph[0] = pack_bf2(sa[0], sa[1]);
                pl[0] = pack_bf2(bf_lo_res(sa[0], ph[0], 0), bf_lo_res(sa[1], ph[0], 1));
                ph[1] = pack_bf2(sa[2], sa[3]);
                pl[1] = pack_bf2(bf_lo_res(sa[2], ph[1], 0), bf_lo_res(sa[3], ph[1], 1));
                ph[2] = pack_bf2(sb[0], sb[1]);
                pl[2] = pack_bf2(bf_lo_res(sb[0], ph[2], 0), bf_lo_res(sb[1], ph[2], 1));
                ph[3] = pack_bf2(sb[2], sb[3]);
                pl[3] = pack_bf2(bf_lo_res(sb[2], ph[3], 0), bf_lo_res(sb[3], ph[3], 1));
            }
            int c = kb * 16 + tig * 2;
#pragma unroll
            for (int nd = 0; nd < 8; nd++) {
                int n = nd * 8 + g;
                uint32_t vh[2], vl[2];
                vh[0] = *(const uint32_t*)(asm_ + SVH + n * AP + c);
                vh[1] = *(const uint32_t*)(asm_ + SVH + n * AP + c + 8);
                vl[0] = *(const uint32_t*)(asm_ + SVL + n * AP + c);
                vl[1] = *(const uint32_t*)(asm_ + SVL + n * AP + c + 8);
                mma_bf16(o[nd], ph, vh);
                mma_bf16(o[nd], pl, vh);
                mma_bf16(o[nd], ph, vl);
            }
        }
        __syncthreads();
    }

    // ---- epilogue: y[row][h*64+col] = o / l ----
    float il0 = 1.0f / l0, il1 = 1.0f / l1;
#pragma unroll
    for (int nd = 0; nd < 8; nd++) {
        int col = h * HD + nd * 8 + tig * 2;
        *(float2*)(y + (size_t)r0 * C_DIM + col) = make_float2(o[nd][0] * il0, o[nd][1] * il0);
        *(float2*)(y + (size_t)r1 * C_DIM + col) = make_float2(o[nd][2] * il1, o[nd][3] * il1);
    }
}

// ---------------- rmsnorm ----------------
__global__ __launch_bounds__(256) void rmsnorm_kernel(const float* __restrict__ x,
                                                      const float* __restrict__ w,
                                                      float* __restrict__ o) {
    int row = blockIdx.x;
    int t = threadIdx.x;
    const float4* xr = (const float4*)(x + (size_t)row * C_DIM);
    float4 v = xr[t];
    float ss = v.x * v.x + v.y * v.y + v.z * v.z + v.w * v.w;
    __shared__ float red[8];
#pragma unroll
    for (int off = 16; off; off >>= 1) ss += __shfl_xor_sync(~0u, ss, off);
    if ((t & 31) == 0) red[t >> 5] = ss;
    __syncthreads();
    if (t < 32) {
        float s2 = (t < 8) ? red[t] : 0.f;
#pragma unroll
        for (int off = 4; off; off >>= 1) s2 += __shfl_xor_sync(~0u, s2, off);
        if (t == 0) red[0] = s2;
    }
    __syncthreads();
    float rn = rsqrtf(red[0] * (1.0f / C_DIM) + 1e-6f);
    float4 wv = ((const float4*)w)[t];
    float4 ov = make_float4(v.x * rn * wv.x, v.y * rn * wv.y, v.z * rn * wv.z, v.w * rn * wv.w);
    ((float4*)(o + (size_t)row * C_DIM))[t] = ov;
}

// ---------------- silu(a) * b ----------------
__global__ __launch_bounds__(256) void silu_mul_kernel(const float* __restrict__ a,
                                                       const float* __restrict__ b,
                                                       float* __restrict__ o, int n4) {
    int i = blockIdx.x * blockDim.x + threadIdx.x;
    if (i < n4) {
        float4 x = ((const float4*)a)[i];
        float4 g = ((const float4*)b)[i];
        float4 r;
        r.x = x.x / (1.f + __expf(-x.x)) * g.x;
        r.y = x.y / (1.f + __expf(-x.y)) * g.y;
        r.z = x.z / (1.f + __expf(-x.z)) * g.z;
        r.w = x.w / (1.f + __expf(-x.w)) * g.w;
        ((float4*)o)[i] = r;
    }
}

// ---------------- orchestration ----------------
extern "C" void kernel_launch(void* const* d_in, const int* in_sizes, int n_in,
                              void* d_out, int out_size) {
    const float* x      = (const float*)d_in[0];
    const float* anw    = (const float*)d_in[1];
    const float* fnw    = (const float*)d_in[2];
    const float* c_attn = (const float*)d_in[3];
    const float* c_proj = (const float*)d_in[4];
    const float* w1     = (const float*)d_in[5];
    const float* w2     = (const float*)d_in[6];
    const float* w3     = (const float*)d_in[7];
    float* out = (float*)d_out;

    float *xn, *qkv, *y, *x2, *xn2, *h1, *h3;
    cudaGetSymbolAddress((void**)&xn,  g_xn);
    cudaGetSymbolAddress((void**)&qkv, g_qkv);
    cudaGetSymbolAddress((void**)&y,   g_y);
    cudaGetSymbolAddress((void**)&x2,  g_x2);
    cudaGetSymbolAddress((void**)&xn2, g_xn2);
    cudaGetSymbolAddress((void**)&h1,  g_h1);
    cudaGetSymbolAddress((void**)&h3,  g_h3);

    cudaFuncSetAttribute(gemm_mma,
                         cudaFuncAttributeMaxDynamicSharedMemorySize, GEMM_SMEM);
    cudaFuncSetAttribute(attn_mma,
                         cudaFuncAttributeMaxDynamicSharedMemorySize, ATTN_SMEM);

    // 1) xn = rmsnorm(x, attn_norm_w)
    rmsnorm_kernel<<<T_DIM, 256>>>(x, anw, xn);

    // 2) qkv = xn @ c_attn^T
    gemm_mma<<<dim3(3 * C_DIM / BN, T_DIM / BM), 256, GEMM_SMEM>>>(
        xn, c_attn, nullptr, qkv, T_DIM, 3 * C_DIM, C_DIM);

    // 3) y = causal_attention(qkv)
    attn_mma<<<dim3(T_DIM / 128, NH), 256, ATTN_SMEM>>>(qkv, y);

    // 4) x2 = y @ c_proj^T + x
    gemm_mma<<<dim3(C_DIM / BN, T_DIM / BM), 256, GEMM_SMEM>>>(
        y, c_proj, x, x2, T_DIM, C_DIM, C_DIM);

    // 5) xn2 = rmsnorm(x2, ffn_norm_w)
    rmsnorm_kernel<<<T_DIM, 256>>>(x2, fnw, xn2);

    // 6) h1 = xn2 @ w1^T ; h3 = xn2 @ w3^T
    gemm_mma<<<dim3(HF_DIM / BN, T_DIM / BM), 256, GEMM_SMEM>>>(
        xn2, w1, nullptr, h1, T_DIM, HF_DIM, C_DIM);
    gemm_mma<<<dim3(HF_DIM / BN, T_DIM / BM), 256, GEMM_SMEM>>>(
        xn2, w3, nullptr, h3, T_DIM, HF_DIM, C_DIM);

    // 7) h1 = silu(h1) * h3
    {
        int n4 = T_DIM * HF_DIM / 4;
        silu_mul_kernel<<<(n4 + 255) / 256, 256>>>(h1, h3, h1, n4);
    }

    // 8) out = h1 @ w2^T + x2
    gemm_mma<<<dim3(C_DIM / BN, T_DIM / BM), 256, GEMM_SMEM>>>(
        h1, w2, x2, out, T_DIM, C_DIM, HF_DIM);
}

// round 5
// speedup vs baseline: 2.7510x; 1.1426x over previous
#include <cuda_runtime.h>
#include <cuda_bf16.h>
#include <cstdint>
#include <math.h>

#define T_DIM 4096
#define C_DIM 1024
#define HF_DIM 4096
#define NH 16
#define HD 64

typedef __nv_bfloat16 bf16;

// ---------------- scratch (module-static, no runtime allocation) ----------------
__device__ float g_qkv[T_DIM * 3 * C_DIM];
__device__ float g_x2 [T_DIM * C_DIM];
__device__ float g_h1 [T_DIM * HF_DIM];
__device__ float g_h3 [T_DIM * HF_DIM];

__device__ bf16 g_xn_h [T_DIM * C_DIM];
__device__ bf16 g_xn_l [T_DIM * C_DIM];
__device__ bf16 g_y_h  [T_DIM * C_DIM];
__device__ bf16 g_y_l  [T_DIM * C_DIM];
__device__ bf16 g_xn2_h[T_DIM * C_DIM];
__device__ bf16 g_xn2_l[T_DIM * C_DIM];
__device__ bf16 g_hg_h [T_DIM * HF_DIM];
__device__ bf16 g_hg_l [T_DIM * HF_DIM];

__device__ bf16 g_wqkv_h[3 * C_DIM * C_DIM];
__device__ bf16 g_wqkv_l[3 * C_DIM * C_DIM];
__device__ bf16 g_wpro_h[C_DIM * C_DIM];
__device__ bf16 g_wpro_l[C_DIM * C_DIM];
__device__ bf16 g_w1_h[HF_DIM * C_DIM];
__device__ bf16 g_w1_l[HF_DIM * C_DIM];
__device__ bf16 g_w2_h[C_DIM * HF_DIM];
__device__ bf16 g_w2_l[C_DIM * HF_DIM];
__device__ bf16 g_w3_h[HF_DIM * C_DIM];
__device__ bf16 g_w3_l[HF_DIM * C_DIM];

// ================= common helpers =================
static __device__ __forceinline__ void mma_bf16(float* c, const uint32_t* a,
                                                const uint32_t* b) {
    asm volatile(
        "mma.sync.aligned.m16n8k16.row.col.f32.bf16.bf16.f32 "
        "{%0,%1,%2,%3}, {%4,%5,%6,%7}, {%8,%9}, {%0,%1,%2,%3};"
        : "+f"(c[0]), "+f"(c[1]), "+f"(c[2]), "+f"(c[3])
        : "r"(a[0]), "r"(a[1]), "r"(a[2]), "r"(a[3]), "r"(b[0]), "r"(b[1]));
}
static __device__ __forceinline__ uint32_t pack_bf2(float x, float y) {
    __nv_bfloat162 h;
    h.x = __float2bfloat16(x);
    h.y = __float2bfloat16(y);
    return *(uint32_t*)&h;
}
static __device__ __forceinline__ float bf_lo_res(float v, uint32_t packed, int hi) {
    __nv_bfloat162* p = (__nv_bfloat162*)&packed;
    return v - __bfloat162float(hi ? p->y : p->x);
}
static __device__ __forceinline__ uint32_t smem_u32(const void* p) {
    uint32_t a;
    asm("{ .reg .u64 t; cvta.to.shared.u64 t, %1; cvt.u32.u64 %0, t; }" : "=r"(a) : "l"(p));
    return a;
}

// ---------------- split fp32 -> (hi, lo) bf16, elementwise ----------------
__global__ __launch_bounds__(256) void split_kernel(const float* __restrict__ in,
                                                    bf16* __restrict__ oh,
                                                    bf16* __restrict__ ol, int n4) {
    int i = blockIdx.x * blockDim.x + threadIdx.x;
    if (i < n4) {
        float4 v = ((const float4*)in)[i];
        uint32_t h01 = pack_bf2(v.x, v.y), h23 = pack_bf2(v.z, v.w);
        uint32_t l01 = pack_bf2(bf_lo_res(v.x, h01, 0), bf_lo_res(v.y, h01, 1));
        uint32_t l23 = pack_bf2(bf_lo_res(v.z, h23, 0), bf_lo_res(v.w, h23, 1));
        ((uint2*)oh)[i] = make_uint2(h01, h23);
        ((uint2*)ol)[i] = make_uint2(l01, l23);
    }
}

// ================= pipelined bf16 GEMM =================
// C[M,N] = (Ah+Al)[M,K] @ (Bh+Bl)[N,K]^T (+ R), split operands preconverted.
// CTA tile 128x128, BK=32, 8 warps (2Mx4N), 2-stage cp.async pipeline.
#define GPITCH 40
#define GARR (128 * GPITCH)          // bf16 elems per array (5120)
#define GSTAGE (4 * GARR)            // per stage (20480 bf16 = 40960 B)
#define GEMM_SMEM (2 * GSTAGE * 2)   // 81920 bytes

__global__ __launch_bounds__(256) void gemm_bf(const bf16* __restrict__ Ah,
                                               const bf16* __restrict__ Al,
                                               const bf16* __restrict__ Bh,
                                               const bf16* __restrict__ Bl,
                                               const float* __restrict__ R,
                                               float* __restrict__ C,
                                               int M, int N, int K) {
    extern __shared__ bf16 sh[];
    const int t = threadIdx.x;
    const int w = t >> 5;
    const int lane = t & 31;
    const int g = lane >> 2;
    const int tig = lane & 3;
    const int wm = w >> 2;
    const int wn = w & 3;

    const int m0 = blockIdx.y << 7;
    const int n0 = blockIdx.x << 7;
    const int nk = K >> 5;
    const uint32_t sbase = smem_u32(sh);

    const bf16* srcs[4] = {Ah + (size_t)m0 * K, Al + (size_t)m0 * K,
                           Bh + (size_t)n0 * K, Bl + (size_t)n0 * K};

    // row/chunk mapping for cp.async (per array: 128 rows x 4 x 16B)
    const int lrow = t >> 2;
    const int lch = (t & 3) << 3;   // bf16 offset within row: 0,8,16,24

    auto load_stage = [&](int i) {
        const int st = i & 1;
        const int k0 = i << 5;
#pragma unroll
        for (int arr = 0; arr < 4; arr++) {
#pragma unroll
            for (int it = 0; it < 2; it++) {
                int row = lrow + (it << 6);
                const bf16* gp = srcs[arr] + (size_t)row * K + k0 + lch;
                uint32_t sa = sbase + (uint32_t)(st * GSTAGE + arr * GARR + row * GPITCH + lch) * 2u;
                asm volatile("cp.async.cg.shared.global [%0], [%1], 16;" :: "r"(sa), "l"(gp));
            }
        }
        asm volatile("cp.async.commit_group;" ::: "memory");
    };

    float acc[4][4][4] = {};
    load_stage(0);

    for (int i = 0; i < nk; i++) {
        if (i + 1 < nk) {
            load_stage(i + 1);
            asm volatile("cp.async.wait_group 1;" ::: "memory");
        } else {
            asm volatile("cp.async.wait_group 0;" ::: "memory");
        }
        __syncthreads();

        const bf16* Ahs = sh + (i & 1) * GSTAGE;
        const bf16* Als = Ahs + GARR;
        const bf16* Bhs = Ahs + 2 * GARR;
        const bf16* Bls = Ahs + 3 * GARR;

#pragma unroll
        for (int kk = 0; kk < 32; kk += 16) {
            uint32_t ahi[4][4], alo[4][4], bhi[4][2], blo[4][2];
#pragma unroll
            for (int mi = 0; mi < 4; mi++) {
                int r = wm * 64 + mi * 16 + g;
                int c = kk + tig * 2;
                ahi[mi][0] = *(const uint32_t*)(Ahs + r * GPITCH + c);
                ahi[mi][1] = *(const uint32_t*)(Ahs + (r + 8) * GPITCH + c);
                ahi[mi][2] = *(const uint32_t*)(Ahs + r * GPITCH + c + 8);
                ahi[mi][3] = *(const uint32_t*)(Ahs + (r + 8) * GPITCH + c + 8);
                alo[mi][0] = *(const uint32_t*)(Als + r * GPITCH + c);
                alo[mi][1] = *(const uint32_t*)(Als + (r + 8) * GPITCH + c);
                alo[mi][2] = *(const uint32_t*)(Als + r * GPITCH + c + 8);
                alo[mi][3] = *(const uint32_t*)(Als + (r + 8) * GPITCH + c + 8);
            }
#pragma unroll
            for (int ni = 0; ni < 4; ni++) {
                int n = wn * 32 + ni * 8 + g;
                int c = kk + tig * 2;
                bhi[ni][0] = *(const uint32_t*)(Bhs + n * GPITCH + c);
                bhi[ni][1] = *(const uint32_t*)(Bhs + n * GPITCH + c + 8);
                blo[ni][0] = *(const uint32_t*)(Bls + n * GPITCH + c);
                blo[ni][1] = *(const uint32_t*)(Bls + n * GPITCH + c + 8);
            }
#pragma unroll
            for (int mi = 0; mi < 4; mi++)
#pragma unroll
                for (int ni = 0; ni < 4; ni++) {
                    mma_bf16(acc[mi][ni], ahi[mi], bhi[ni]);
                    mma_bf16(acc[mi][ni], ahi[mi], blo[ni]);
                    mma_bf16(acc[mi][ni], alo[mi], bhi[ni]);
                }
        }
        __syncthreads();
    }

#pragma unroll
    for (int mi = 0; mi < 4; mi++) {
        int r = m0 + wm * 64 + mi * 16 + g;
#pragma unroll
        for (int ni = 0; ni < 4; ni++) {
            int col = n0 + wn * 32 + ni * 8 + tig * 2;
            float2 v0 = make_float2(acc[mi][ni][0], acc[mi][ni][1]);
            float2 v1 = make_float2(acc[mi][ni][2], acc[mi][ni][3]);
            size_t o0 = (size_t)r * N + col;
            size_t o1 = (size_t)(r + 8) * N + col;
            if (R) {
                float2 r0 = *(const float2*)(R + o0);
                float2 r1 = *(const float2*)(R + o1);
                v0.x += r0.x; v0.y += r0.y;
                v1.x += r1.x; v1.y += r1.y;
            }
            *(float2*)(C + o0) = v0;
            *(float2*)(C + o1) = v1;
        }
    }
}

// ================= tensor-core flash attention (split bf16, writes split y) =================
#define AP 72
#define SQH 0
#define SQL (128 * AP)
#define SKH (256 * AP)
#define SKL (320 * AP)
#define SVH (384 * AP)
#define SVL (448 * AP)
#define ATTN_SMEM (512 * AP * 2)

__global__ __launch_bounds__(256) void attn_mma(const float* __restrict__ qkv,
                                                bf16* __restrict__ yh,
                                                bf16* __restrict__ yl) {
    extern __shared__ bf16 asm_[];
    const int h = blockIdx.y;
    const int q0 = blockIdx.x << 7;
    const int t = threadIdx.x;
    const int w = t >> 5;
    const int lane = t & 31;
    const int g = lane >> 2;
    const int tig = lane & 3;

#pragma unroll
    for (int it = 0; it < 8; it++) {
        int idx = t + (it << 8);
        int row = idx >> 4, c4 = idx & 15;
        float4 v = *(const float4*)(qkv + (size_t)(q0 + row) * (3 * C_DIM) + h * HD + (c4 << 2));
        v.x *= 0.125f; v.y *= 0.125f; v.z *= 0.125f; v.w *= 0.125f;
        uint32_t h01 = pack_bf2(v.x, v.y), h23 = pack_bf2(v.z, v.w);
        uint32_t l01 = pack_bf2(bf_lo_res(v.x, h01, 0), bf_lo_res(v.y, h01, 1));
        uint32_t l23 = pack_bf2(bf_lo_res(v.z, h23, 0), bf_lo_res(v.w, h23, 1));
        int off = row * AP + (c4 << 2);
        *(uint2*)(asm_ + SQH + off) = make_uint2(h01, h23);
        *(uint2*)(asm_ + SQL + off) = make_uint2(l01, l23);
    }
    __syncthreads();

    uint32_t qh[4][4], ql[4][4];
    {
        int r = w * 16 + g;
#pragma unroll
        for (int ks = 0; ks < 4; ks++) {
            int c = ks * 16 + tig * 2;
            qh[ks][0] = *(const uint32_t*)(asm_ + SQH + r * AP + c);
            qh[ks][1] = *(const uint32_t*)(asm_ + SQH + (r + 8) * AP + c);
            qh[ks][2] = *(const uint32_t*)(asm_ + SQH + r * AP + c + 8);
            qh[ks][3] = *(const uint32_t*)(asm_ + SQH + (r + 8) * AP + c + 8);
            ql[ks][0] = *(const uint32_t*)(asm_ + SQL + r * AP + c);
            ql[ks][1] = *(const uint32_t*)(asm_ + SQL + (r + 8) * AP + c);
            ql[ks][2] = *(const uint32_t*)(asm_ + SQL + r * AP + c + 8);
            ql[ks][3] = *(const uint32_t*)(asm_ + SQL + (r + 8) * AP + c + 8);
        }
    }

    float o[8][4] = {};
    float m0 = -1e30f, m1 = -1e30f, l0 = 0.f, l1 = 0.f;
    const int ntile = (q0 >> 6) + 2;
    const int r0 = q0 + w * 16 + g;
    const int r1 = r0 + 8;

    for (int jt = 0; jt < ntile; jt++) {
        const int j0 = jt << 6;
#pragma unroll
        for (int it = 0; it < 4; it++) {
            int idx = t + (it << 8);
            int row = idx >> 4, c4 = idx & 15;
            float4 v = *(const float4*)(qkv + (size_t)(j0 + row) * (3 * C_DIM) + C_DIM + h * HD + (c4 << 2));
            uint32_t h01 = pack_bf2(v.x, v.y), h23 = pack_bf2(v.z, v.w);
            uint32_t l01 = pack_bf2(bf_lo_res(v.x, h01, 0), bf_lo_res(v.y, h01, 1));
            uint32_t l23 = pack_bf2(bf_lo_res(v.z, h23, 0), bf_lo_res(v.w, h23, 1));
            int off = row * AP + (c4 << 2);
            *(uint2*)(asm_ + SKH + off) = make_uint2(h01, h23);
            *(uint2*)(asm_ + SKL + off) = make_uint2(l01, l23);
        }
#pragma unroll
        for (int it = 0; it < 4; it++) {
            int idx = t + (it << 8);
            int row = idx >> 4, c4 = idx & 15;
            float4 v = *(const float4*)(qkv + (size_t)(j0 + row) * (3 * C_DIM) + 2 * C_DIM + h * HD + (c4 << 2));
            float vv[4] = {v.x, v.y, v.z, v.w};
#pragma unroll
            for (int i = 0; i < 4; i++) {
                int d = (c4 << 2) + i;
                bf16 hb = __float2bfloat16(vv[i]);
                asm_[SVH + d * AP + row] = hb;
                asm_[SVL + d * AP + row] = __float2bfloat16(vv[i] - __bfloat162float(hb));
            }
        }
        __syncthreads();

        float s[8][4];
#pragma unroll
        for (int nb = 0; nb < 8; nb++) {
            s[nb][0] = 0.f; s[nb][1] = 0.f; s[nb][2] = 0.f; s[nb][3] = 0.f;
            int n = nb * 8 + g;
#pragma unroll
            for (int ks = 0; ks < 4; ks++) {
                int c = ks * 16 + tig * 2;
                uint32_t bh[2], bl[2];
                bh[0] = *(const uint32_t*)(asm_ + SKH + n * AP + c);
                bh[1] = *(const uint32_t*)(asm_ + SKH + n * AP + c + 8);
                bl[0] = *(const uint32_t*)(asm_ + SKL + n * AP + c);
                bl[1] = *(const uint32_t*)(asm_ + SKL + n * AP + c + 8);
                mma_bf16(s[nb], qh[ks], bh);
                mma_bf16(s[nb], qh[ks], bl);
                mma_bf16(s[nb], ql[ks], bh);
            }
        }

        if (jt >= ntile - 2) {
#pragma unroll
            for (int nb = 0; nb < 8; nb++) {
                int c0 = j0 + nb * 8 + tig * 2;
                if (c0 > r0)     s[nb][0] = -1e30f;
                if (c0 + 1 > r0) s[nb][1] = -1e30f;
                if (c0 > r1)     s[nb][2] = -1e30f;
                if (c0 + 1 > r1) s[nb][3] = -1e30f;
            }
        }

        float tm0 = -1e30f, tm1 = -1e30f;
#pragma unroll
        for (int nb = 0; nb < 8; nb++) {
            tm0 = fmaxf(tm0, fmaxf(s[nb][0], s[nb][1]));
            tm1 = fmaxf(tm1, fmaxf(s[nb][2], s[nb][3]));
        }
        tm0 = fmaxf(tm0, __shfl_xor_sync(~0u, tm0, 1));
        tm0 = fmaxf(tm0, __shfl_xor_sync(~0u, tm0, 2));
        tm1 = fmaxf(tm1, __shfl_xor_sync(~0u, tm1, 1));
        tm1 = fmaxf(tm1, __shfl_xor_sync(~0u, tm1, 2));
        float nm0 = fmaxf(m0, tm0), nm1 = fmaxf(m1, tm1);
        float a0 = __expf(m0 - nm0), a1 = __expf(m1 - nm1);
        m0 = nm0; m1 = nm1;
        float rs0 = 0.f, rs1 = 0.f;
#pragma unroll
        for (int nb = 0; nb < 8; nb++) {
            s[nb][0] = __expf(s[nb][0] - nm0);
            s[nb][1] = __expf(s[nb][1] - nm0);
            s[nb][2] = __expf(s[nb][2] - nm1);
            s[nb][3] = __expf(s[nb][3] - nm1);
            rs0 += s[nb][0] + s[nb][1];
            rs1 += s[nb][2] + s[nb][3];
        }
        rs0 += __shfl_xor_sync(~0u, rs0, 1);
        rs0 += __shfl_xor_sync(~0u, rs0, 2);
        rs1 += __shfl_xor_sync(~0u, rs1, 1);
        rs1 += __shfl_xor_sync(~0u, rs1, 2);
        l0 = l0 * a0 + rs0;
        l1 = l1 * a1 + rs1;
#pragma unroll
        for (int nd = 0; nd < 8; nd++) {
            o[nd][0] *= a0; o[nd][1] *= a0; o[nd][2] *= a1; o[nd][3] *= a1;
        }

#pragma unroll
        for (int kb = 0; kb < 4; kb++) {
            uint32_t ph[4], pl[4];
            {
                float* sa = s[2 * kb];
                float* sb = s[2 * kb + 1];
                ph[0] = pack_bf2(sa[0], sa[1]);
                pl[0] = pack_bf2(bf_lo_res(sa[0], ph[0], 0), bf_lo_res(sa[1], ph[0], 1));
                ph[1] = pack_bf2(sa[2], sa[3]);
                pl[1] = pack_bf2(bf_lo_res(sa[2], ph[1], 0), bf_lo_res(sa[3], ph[1], 1));
                ph[2] = pack_bf2(sb[0], sb[1]);
                pl[2] = pack_bf2(bf_lo_res(sb[0], ph[2], 0), bf_lo_res(sb[1], ph[2], 1));
                ph[3] = pack_bf2(sb[2], sb[3]);
                pl[3] = pack_bf2(bf_lo_res(sb[2], ph[3], 0), bf_lo_res(sb[3], ph[3], 1));
            }
            int c = kb * 16 + tig * 2;
#pragma unroll
            for (int nd = 0; nd < 8; nd++) {
                int n = nd * 8 + g;
                uint32_t vh[2], vl[2];
                vh[0] = *(const uint32_t*)(asm_ + SVH + n * AP + c);
                vh[1] = *(const uint32_t*)(asm_ + SVH + n * AP + c + 8);
                vl[0] = *(const uint32_t*)(asm_ + SVL + n * AP + c);
                vl[1] = *(const uint32_t*)(asm_ + SVL + n * AP + c + 8);
                mma_bf16(o[nd], ph, vh);
                mma_bf16(o[nd], pl, vh);
                mma_bf16(o[nd], ph, vl);
            }
        }
        __syncthreads();
    }

    // ---- epilogue: write split y ----
    float il0 = 1.0f / l0, il1 = 1.0f / l1;
#pragma unroll
    for (int nd = 0; nd < 8; nd++) {
        int col = h * HD + nd * 8 + tig * 2;
        float v00 = o[nd][0] * il0, v01 = o[nd][1] * il0;
        float v10 = o[nd][2] * il1, v11 = o[nd][3] * il1;
        uint32_t h0 = pack_bf2(v00, v01);
        uint32_t l0p = pack_bf2(bf_lo_res(v00, h0, 0), bf_lo_res(v01, h0, 1));
        uint32_t h1v = pack_bf2(v10, v11);
        uint32_t l1p = pack_bf2(bf_lo_res(v10, h1v, 0), bf_lo_res(v11, h1v, 1));
        *(uint32_t*)(yh + (size_t)r0 * C_DIM + col) = h0;
        *(uint32_t*)(yl + (size_t)r0 * C_DIM + col) = l0p;
        *(uint32_t*)(yh + (size_t)r1 * C_DIM + col) = h1v;
        *(uint32_t*)(yl + (size_t)r1 * C_DIM + col) = l1p;
    }
}

// ---------------- rmsnorm -> split bf16 ----------------
__global__ __launch_bounds__(256) void rmsnorm_split(const float* __restrict__ x,
                                                     const float* __restrict__ w,
                                                     bf16* __restrict__ oh,
                                                     bf16* __restrict__ ol) {
    int row = blockIdx.x;
    int t = threadIdx.x;
    const float4* xr = (const float4*)(x + (size_t)row * C_DIM);
    float4 v = xr[t];
    float ss = v.x * v.x + v.y * v.y + v.z * v.z + v.w * v.w;
    __shared__ float red[8];
#pragma unroll
    for (int off = 16; off; off >>= 1) ss += __shfl_xor_sync(~0u, ss, off);
    if ((t & 31) == 0) red[t >> 5] = ss;
    __syncthreads();
    if (t < 32) {
        float s2 = (t < 8) ? red[t] : 0.f;
#pragma unroll
        for (int off = 4; off; off >>= 1) s2 += __shfl_xor_sync(~0u, s2, off);
        if (t == 0) red[0] = s2;
    }
    __syncthreads();
    float rn = rsqrtf(red[0] * (1.0f / C_DIM) + 1e-6f);
    float4 wv = ((const float4*)w)[t];
    float4 ov = make_float4(v.x * rn * wv.x, v.y * rn * wv.y, v.z * rn * wv.z, v.w * rn * wv.w);
    uint32_t h01 = pack_bf2(ov.x, ov.y), h23 = pack_bf2(ov.z, ov.w);
    uint32_t l01 = pack_bf2(bf_lo_res(ov.x, h01, 0), bf_lo_res(ov.y, h01, 1));
    uint32_t l23 = pack_bf2(bf_lo_res(ov.z, h23, 0), bf_lo_res(ov.w, h23, 1));
    ((uint2*)(oh + (size_t)row * C_DIM))[t] = make_uint2(h01, h23);
    ((uint2*)(ol + (size_t)row * C_DIM))[t] = make_uint2(l01, l23);
}

// ---------------- silu(a) * b -> split bf16 ----------------
__global__ __launch_bounds__(256) void silu_mul_split(const float* __restrict__ a,
                                                      const float* __restrict__ b,
                                                      bf16* __restrict__ oh,
                                                      bf16* __restrict__ ol, int n4) {
    int i = blockIdx.x * blockDim.x + threadIdx.x;
    if (i < n4) {
        float4 x = ((const float4*)a)[i];
        float4 g = ((const float4*)b)[i];
        float4 r;
        r.x = x.x / (1.f + __expf(-x.x)) * g.x;
        r.y = x.y / (1.f + __expf(-x.y)) * g.y;
        r.z = x.z / (1.f + __expf(-x.z)) * g.z;
        r.w = x.w / (1.f + __expf(-x.w)) * g.w;
        uint32_t h01 = pack_bf2(r.x, r.y), h23 = pack_bf2(r.z, r.w);
        uint32_t l01 = pack_bf2(bf_lo_res(r.x, h01, 0), bf_lo_res(r.y, h01, 1));
        uint32_t l23 = pack_bf2(bf_lo_res(r.z, h23, 0), bf_lo_res(r.w, h23, 1));
        ((uint2*)oh)[i] = make_uint2(h01, h23);
        ((uint2*)ol)[i] = make_uint2(l01, l23);
    }
}

// ---------------- orchestration ----------------
extern "C" void kernel_launch(void* const* d_in, const int* in_sizes, int n_in,
                              void* d_out, int out_size) {
    const float* x      = (const float*)d_in[0];
    const float* anw    = (const float*)d_in[1];
    const float* fnw    = (const float*)d_in[2];
    const float* c_attn = (const float*)d_in[3];
    const float* c_proj = (const float*)d_in[4];
    const float* w1     = (const float*)d_in[5];
    const float* w2     = (const float*)d_in[6];
    const float* w3     = (const float*)d_in[7];
    float* out = (float*)d_out;

    float *qkv, *x2, *h1, *h3;
    bf16 *xnh, *xnl, *yh, *yl, *xn2h, *xn2l, *hgh, *hgl;
    bf16 *wqh, *wql, *wph, *wpl, *w1h, *w1l, *w2h, *w2l, *w3h, *w3l;
    cudaGetSymbolAddress((void**)&qkv,  g_qkv);
    cudaGetSymbolAddress((void**)&x2,   g_x2);
    cudaGetSymbolAddress((void**)&h1,   g_h1);
    cudaGetSymbolAddress((void**)&h3,   g_h3);
    cudaGetSymbolAddress((void**)&xnh,  g_xn_h);
    cudaGetSymbolAddress((void**)&xnl,  g_xn_l);
    cudaGetSymbolAddress((void**)&yh,   g_y_h);
    cudaGetSymbolAddress((void**)&yl,   g_y_l);
    cudaGetSymbolAddress((void**)&xn2h, g_xn2_h);
    cudaGetSymbolAddress((void**)&xn2l, g_xn2_l);
    cudaGetSymbolAddress((void**)&hgh,  g_hg_h);
    cudaGetSymbolAddress((void**)&hgl,  g_hg_l);
    cudaGetSymbolAddress((void**)&wqh,  g_wqkv_h);
    cudaGetSymbolAddress((void**)&wql,  g_wqkv_l);
    cudaGetSymbolAddress((void**)&wph,  g_wpro_h);
    cudaGetSymbolAddress((void**)&wpl,  g_wpro_l);
    cudaGetSymbolAddress((void**)&w1h,  g_w1_h);
    cudaGetSymbolAddress((void**)&w1l,  g_w1_l);
    cudaGetSymbolAddress((void**)&w2h,  g_w2_h);
    cudaGetSymbolAddress((void**)&w2l,  g_w2_l);
    cudaGetSymbolAddress((void**)&w3h,  g_w3_h);
    cudaGetSymbolAddress((void**)&w3l,  g_w3_l);

    cudaFuncSetAttribute(gemm_bf,
                         cudaFuncAttributeMaxDynamicSharedMemorySize, GEMM_SMEM);
    cudaFuncSetAttribute(attn_mma,
                         cudaFuncAttributeMaxDynamicSharedMemorySize, ATTN_SMEM);

    // 0) split weights
    split_kernel<<<3 * C_DIM * C_DIM / 1024, 256>>>(c_attn, wqh, wql, 3 * C_DIM * C_DIM / 4);
    split_kernel<<<C_DIM * C_DIM / 1024, 256>>>(c_proj, wph, wpl, C_DIM * C_DIM / 4);
    split_kernel<<<HF_DIM * C_DIM / 1024, 256>>>(w1, w1h, w1l, HF_DIM * C_DIM / 4);
    split_kernel<<<C_DIM * HF_DIM / 1024, 256>>>(w2, w2h, w2l, C_DIM * HF_DIM / 4);
    split_kernel<<<HF_DIM * C_DIM / 1024, 256>>>(w3, w3h, w3l, HF_DIM * C_DIM / 4);

    // 1) xn = rmsnorm(x) -> split
    rmsnorm_split<<<T_DIM, 256>>>(x, anw, xnh, xnl);

    // 2) qkv = xn @ c_attn^T
    gemm_bf<<<dim3(3 * C_DIM / 128, T_DIM / 128), 256, GEMM_SMEM>>>(
        xnh, xnl, wqh, wql, nullptr, qkv, T_DIM, 3 * C_DIM, C_DIM);

    // 3) y = attention(qkv) -> split
    attn_mma<<<dim3(T_DIM / 128, NH), 256, ATTN_SMEM>>>(qkv, yh, yl);

    // 4) x2 = y @ c_proj^T + x
    gemm_bf<<<dim3(C_DIM / 128, T_DIM / 128), 256, GEMM_SMEM>>>(
        yh, yl, wph, wpl, x, x2, T_DIM, C_DIM, C_DIM);

    // 5) xn2 = rmsnorm(x2) -> split
    rmsnorm_split<<<T_DIM, 256>>>(x2, fnw, xn2h, xn2l);

    // 6) h1 = xn2 @ w1^T ; h3 = xn2 @ w3^T
    gemm_bf<<<dim3(HF_DIM / 128, T_DIM / 128), 256, GEMM_SMEM>>>(
        xn2h, xn2l, w1h, w1l, nullptr, h1, T_DIM, HF_DIM, C_DIM);
    gemm_bf<<<dim3(HF_DIM / 128, T_DIM / 128), 256, GEMM_SMEM>>>(
        xn2h, xn2l, w3h, w3l, nullptr, h3, T_DIM, HF_DIM, C_DIM);

    // 7) hg = silu(h1) * h3 -> split
    {
        int n4 = T_DIM * HF_DIM / 4;
        silu_mul_split<<<(n4 + 255) / 256, 256>>>(h1, h3, hgh, hgl, n4);
    }

    // 8) out = hg @ w2^T + x2
    gemm_bf<<<dim3(C_DIM / 128, T_DIM / 128), 256, GEMM_SMEM>>>(
        hgh, hgl, w2h, w2l, x2, out, T_DIM, C_DIM, HF_DIM);
}